// round 11
// baseline (speedup 1.0000x reference)
#include <cuda_runtime.h>
#include <cuda_bf16.h>
#include <cstdint>
#include <cstddef>

// ============================================================================
// CustomContrastiveLoss via mma.sync bf16 + fixed-reference base-2 sum-exp.
// (tcgen05 unavailable: harness PTX targets compute_103 without 'a' suffix.)
//
//   loss = mean_i sum_{j: ad_j==ad_i & valid} min(lse2_i - t_ij, -log2(1e-12))
//   t = (logits*log2e) @ labels^T,  lse2_i = log2 sum_j 2^{t_ij}  (masked)
//
// R11 changes vs R10 (113.1us):
//  - k_lse_mma: 512 threads, 4x4 warp grid (warp tile 32x32) -> ~75 regs,
//    4 warps/SMSP with NO register cap / spills (R10's launch_bounds(256,2)
//    forced spills that cancelled the occupancy gain).
//  - mask folded into B during conversion (invalid cols zeroed => contribute
//    2^-64 each to S, rel error < 2^-40): bias smem path deleted entirely.
//  - k_prep: 4 independent float4-pairs per thread (MLP 8) -> latency-bound
//    16.4us -> ~5us.
// ============================================================================

#define NT       8192
#define DD       128
#define TM       128
#define TN       128
#define NSTRIPE  4
#define CSPAN    (NT / NSTRIPE)     // 2048
#define TILES    (CSPAN / TN)       // 16
#define GROWS    16
#define LCAP     2048

#define LOG2E   1.4426950408889634f
#define CAPV    39.863137f
#define M0      64.0f
#define NEG_INF (__int_as_float(0xff800000))

// dynamic smem layout
#define A_OFF    0                  // 128 x 128 bf16 = 32768
#define B_OFF    32768              // 2 bufs x 32768
#define RED_OFF  98304              // 4 x 128 f32 = 2048
#define SMEM_SZ  100352

// device scratch
__device__ __nv_bfloat16 g_Abf[NT * DD];   // logits * log2e, bf16
__device__ __nv_bfloat16 g_Bbf[NT * DD];   // labels (masked), bf16
__device__ float     g_ps[NSTRIPE * NT];   // per-stripe sum of 2^(t-M0)
__device__ long long g_key[NT];
__device__ float     g_loss;
__device__ unsigned  g_done;

__device__ __forceinline__ float ex2(float x) {
    float y; asm("ex2.approx.f32 %0, %1;" : "=f"(y) : "f"(x)); return y;
}
__device__ __forceinline__ float lg2(float x) {
    float y; asm("lg2.approx.f32 %0, %1;" : "=f"(y) : "f"(x)); return y;
}
__device__ __forceinline__ uint32_t s2u(const void* p) {
    uint32_t a;
    asm("{ .reg .u64 t; cvta.to.shared.u64 t, %1; cvt.u32.u64 %0, t; }" : "=r"(a) : "l"(p));
    return a;
}
__device__ __forceinline__ void cpa16(uint32_t dst, const void* src) {
    asm volatile("cp.async.cg.shared.global [%0], [%1], 16;" :: "r"(dst), "l"(src) : "memory");
}
__device__ __forceinline__ void cp_commit() {
    asm volatile("cp.async.commit_group;" ::: "memory");
}
template<int N> __device__ __forceinline__ void cp_wait() {
    asm volatile("cp.async.wait_group %0;" :: "n"(N) : "memory");
}
__device__ __forceinline__ void ldsm4(uint32_t* r, uint32_t addr) {
    asm volatile("ldmatrix.sync.aligned.m8n8.x4.shared.b16 {%0, %1, %2, %3}, [%4];"
                 : "=r"(r[0]), "=r"(r[1]), "=r"(r[2]), "=r"(r[3]) : "r"(addr));
}
__device__ __forceinline__ void mma16816(float* c, const uint32_t* a, const uint32_t* b) {
    asm volatile(
        "mma.sync.aligned.m16n8k16.row.col.f32.bf16.bf16.f32 "
        "{%0, %1, %2, %3}, {%4, %5, %6, %7}, {%8, %9}, {%0, %1, %2, %3};"
        : "+f"(c[0]), "+f"(c[1]), "+f"(c[2]), "+f"(c[3])
        : "r"(a[0]), "r"(a[1]), "r"(a[2]), "r"(a[3]), "r"(b[0]), "r"(b[1]));
}
// XOR-swizzled byte offset inside a [row][128 bf16] tile: chunk = 16B unit 0..15
__device__ __forceinline__ uint32_t swz(int row, int chunk) {
    return (uint32_t)(row * 256 + (((chunk ^ (row & 7)) & 15) << 4));
}

// ---------------------------------------------------------------------------
// k_prep: blocks 0..255 convert fp32 -> bf16, 4 float4-pairs per thread
//         (A scaled by log2e; B zeroed where column invalid).
//         block 256 detects int64-vs-int32 ad dtype, builds keys, zeros accums.
// ---------------------------------------------------------------------------
__global__ __launch_bounds__(256)
void k_prep(const float* __restrict__ logits,
            const float* __restrict__ labels,
            const void*  __restrict__ ad,
            const int*   __restrict__ mask) {
    const int tid = threadIdx.x;
    if (blockIdx.x < 256) {
        const float4* L4 = (const float4*)logits;
        const float4* B4 = (const float4*)labels;
        float4 a[4], b[4];
        float  mv[4];
        int idx0 = blockIdx.x * 1024 + tid;
        #pragma unroll
        for (int it = 0; it < 4; ++it) {
            int idx = idx0 + it * 256;
            a[it] = L4[idx];
            b[it] = B4[idx];
            mv[it] = mask[idx >> 5] ? 1.0f : 0.0f;   // 32 float4 per row
        }
        #pragma unroll
        for (int it = 0; it < 4; ++it) {
            int idx = idx0 + it * 256;
            __nv_bfloat162 a0 = __floats2bfloat162_rn(a[it].x * LOG2E, a[it].y * LOG2E);
            __nv_bfloat162 a1 = __floats2bfloat162_rn(a[it].z * LOG2E, a[it].w * LOG2E);
            __nv_bfloat162 b0 = __floats2bfloat162_rn(b[it].x * mv[it], b[it].y * mv[it]);
            __nv_bfloat162 b1 = __floats2bfloat162_rn(b[it].z * mv[it], b[it].w * mv[it]);
            uint2 ua, ub;
            ua.x = *(uint32_t*)&a0; ua.y = *(uint32_t*)&a1;
            ub.x = *(uint32_t*)&b0; ub.y = *(uint32_t*)&b1;
            ((uint2*)g_Abf)[idx] = ua;
            ((uint2*)g_Bbf)[idx] = ub;
        }
    } else {
        __shared__ int ok;
        if (tid == 0) { ok = 1; g_loss = 0.0f; g_done = 0u; }
        __syncthreads();
        const int* a32 = (const int*)ad;
        int bad = 0;
        for (int i = tid; i < NT / 2; i += 256)    // stays inside 32KB either way
            if (a32[2 * i + 1] != 0) bad = 1;
        if (bad) atomicExch(&ok, 0);
        __syncthreads();
        const int is64 = ok;
        for (int j = tid; j < NT; j += 256) {
            long long v = is64 ? ((const long long*)ad)[j]
                               : (long long)((const int*)ad)[j];
            if (mask[j] == 0) v = (long long)0x8000000000000000ULL + j;
            g_key[j] = v;
        }
    }
}

// ---------------------------------------------------------------------------
// k_lse_mma: 512 threads, warp grid 4(M) x 4(N), warp tile 32x32.
// Invalid columns are already zero in g_Bbf -> t=0 -> 2^-64 contribution.
// ---------------------------------------------------------------------------
__global__ __launch_bounds__(512, 1)
void k_lse_mma() {
    extern __shared__ char sm[];
    const int tid  = threadIdx.x;
    const int lane = tid & 31;
    const int wid  = tid >> 5;       // 0..15
    const int wm   = wid & 3;        // M quarter (rows 32*wm ..)
    const int wn   = wid >> 2;       // N quarter (cols 32*wn ..)
    const int row0 = blockIdx.x * TM;
    const int colbase = blockIdx.y * CSPAN;
    const uint32_t smb = s2u(sm);

    // A tile (once) + B tile 0, via cp.async (512 thr x 4 = 2048 cpa16 each)
    {
        const char* gA = (const char*)g_Abf + (size_t)row0 * 256;
        const char* gB = (const char*)g_Bbf + (size_t)colbase * 256;
        const int r0 = tid >> 4, ch = tid & 15;   // r0 0..31
        #pragma unroll
        for (int it = 0; it < 4; ++it) {
            int r = r0 + it * 32;
            cpa16(smb + A_OFF + swz(r, ch), gA + (size_t)r * 256 + ch * 16);
        }
        #pragma unroll
        for (int it = 0; it < 4; ++it) {
            int r = r0 + it * 32;
            cpa16(smb + B_OFF + swz(r, ch), gB + (size_t)r * 256 + ch * 16);
        }
    }
    cp_commit();

    float ssl[4];
    #pragma unroll
    for (int i = 0; i < 4; ++i) ssl[i] = 0.0f;

    for (int t = 0; t < TILES; ++t) {
        const int buf = t & 1;
        if (t + 1 < TILES) {
            const int nb = buf ^ 1;
            const char* gB = (const char*)g_Bbf + (size_t)(colbase + (t + 1) * TN) * 256;
            const int r0 = tid >> 4, ch = tid & 15;
            #pragma unroll
            for (int it = 0; it < 4; ++it) {
                int r = r0 + it * 32;
                cpa16(smb + B_OFF + nb * 32768 + swz(r, ch), gB + (size_t)r * 256 + ch * 16);
            }
            cp_commit();
            cp_wait<1>();
        } else {
            cp_wait<0>();
        }
        __syncthreads();

        // ---- GEMM: 32x32 warp tile, K=128 ----
        const uint32_t Ab = smb + A_OFF;
        const uint32_t Bb = smb + B_OFF + buf * 32768;
        float c[2][4][4];
        #pragma unroll
        for (int mi = 0; mi < 2; ++mi)
            #pragma unroll
            for (int nj = 0; nj < 4; ++nj)
                #pragma unroll
                for (int e = 0; e < 4; ++e) c[mi][nj][e] = 0.0f;

        #pragma unroll
        for (int kk = 0; kk < 8; ++kk) {
            const int cs = kk * 2 + (lane >> 4);
            uint32_t af[2][4], bfr[2][4];
            #pragma unroll
            for (int mi = 0; mi < 2; ++mi) {
                int r = wm * 32 + mi * 16 + (lane & 15);
                ldsm4(af[mi], Ab + swz(r, cs));
            }
            #pragma unroll
            for (int nb2 = 0; nb2 < 2; ++nb2) {
                int r = wn * 32 + nb2 * 16 + (lane & 15);
                ldsm4(bfr[nb2], Bb + swz(r, cs));
            }
            #pragma unroll
            for (int mi = 0; mi < 2; ++mi) {
                #pragma unroll
                for (int nb2 = 0; nb2 < 2; ++nb2) {
                    uint32_t b0[2] = { bfr[nb2][0], bfr[nb2][2] };
                    uint32_t b1[2] = { bfr[nb2][1], bfr[nb2][3] };
                    mma16816(c[mi][nb2 * 2 + 0], af[mi], b0);
                    mma16816(c[mi][nb2 * 2 + 1], af[mi], b1);
                }
            }
        }

        // ---- epilogue: fixed reference M0; pure accumulate ----
        #pragma unroll
        for (int mi = 0; mi < 2; ++mi) {
            #pragma unroll
            for (int h = 0; h < 2; ++h) {
                float p = 0.0f;
                #pragma unroll
                for (int nj = 0; nj < 4; ++nj) {
                    p += ex2(c[mi][nj][2 * h]     - M0);
                    p += ex2(c[mi][nj][2 * h + 1] - M0);
                }
                ssl[mi * 2 + h] += p;
            }
        }
        __syncthreads();   // buf may be overwritten by next iter's prefetch
    }

    // ---- quad sum (4 lanes sharing a row), then combine 4 column-warps ----
    float* rs = (float*)(sm + RED_OFF);      // [4][128]
    #pragma unroll
    for (int slot = 0; slot < 4; ++slot) {
        float s = ssl[slot];
        s += __shfl_xor_sync(0xffffffffu, s, 1);
        s += __shfl_xor_sync(0xffffffffu, s, 2);
        if ((lane & 3) == 0) {
            int row = wm * 32 + (slot >> 1) * 16 + (slot & 1) * 8 + (lane >> 2);
            rs[wn * 128 + row] = s;
        }
    }
    __syncthreads();
    if (tid < TM) {
        float S = rs[tid] + rs[128 + tid] + rs[256 + tid] + rs[384 + tid];
        g_ps[blockIdx.y * NT + row0 + tid] = S;
    }
}

// ---------------------------------------------------------------------------
// k_pairs: computes lse2 for its rows from stripe sums, scans all keys once
// per block, recomputes positive dots, accumulates loss; last block finalizes.
// ---------------------------------------------------------------------------
__global__ __launch_bounds__(256)
void k_pairs(const float* __restrict__ logits,
             const float* __restrict__ labels,
             const int*   __restrict__ mask,
             float*       __restrict__ out) {
    __shared__ __align__(16) float qs[GROWS * DD];
    __shared__ long long rkey[GROWS];
    __shared__ float     rlse[GROWS];
    __shared__ int       rval[GROWS];
    __shared__ int       list[LCAP];
    __shared__ int       cnt;

    const int tid = threadIdx.x;
    const int row0 = blockIdx.x * GROWS;

    #pragma unroll
    for (int i = 0; i < GROWS * DD / 256; ++i) {
        int idx = tid + i * 256;
        qs[idx] = logits[row0 * DD + idx];
    }
    if (tid < GROWS) {
        int row = row0 + tid;
        rkey[tid] = g_key[row];
        rval[tid] = mask[row];
        float S = 0.0f;
        #pragma unroll
        for (int st = 0; st < NSTRIPE; ++st) S += g_ps[st * NT + row];
        rlse[tid] = (S > 0.0f) ? (lg2(S) + M0) : NEG_INF;
    }
    if (tid == 0) cnt = 0;
    __syncthreads();

    for (int j = tid; j < NT; j += 256) {
        long long kj = g_key[j];
        #pragma unroll
        for (int r = 0; r < GROWS; ++r) {
            if (rval[r] && kj == rkey[r]) {
                int p = atomicAdd(&cnt, 1);
                if (p < LCAP) {
                    list[p] = r * NT + j;
                } else {
                    float d = 0.0f;
                    for (int k = 0; k < DD; ++k)
                        d += qs[r * DD + k] * labels[j * DD + k];
                    atomicAdd(&g_loss, fminf(rlse[r] - d * LOG2E, CAPV));
                }
            }
        }
    }
    __syncthreads();

    const int count = min(cnt, LCAP);
    const int w = tid >> 5, lane = tid & 31;
    float wsum = 0.0f;
    for (int e = w; e < count; e += 8) {
        int ent = list[e];
        int r = ent >> 13;
        int j = ent & (NT - 1);
        float4 q  = *(const float4*)(qs + r * DD + lane * 4);
        float4 lv = *(const float4*)(labels + j * DD + lane * 4);
        float d = q.x * lv.x + q.y * lv.y + q.z * lv.z + q.w * lv.w;
        d += __shfl_xor_sync(0xffffffffu, d, 16);
        d += __shfl_xor_sync(0xffffffffu, d, 8);
        d += __shfl_xor_sync(0xffffffffu, d, 4);
        d += __shfl_xor_sync(0xffffffffu, d, 2);
        d += __shfl_xor_sync(0xffffffffu, d, 1);
        if (lane == 0) wsum += fminf(rlse[r] - d * LOG2E, CAPV);
    }
    if (lane == 0) atomicAdd(&g_loss, wsum);

    // last block to finish writes the final mean (and resets for graph replay)
    __syncthreads();
    if (tid == 0) {
        __threadfence();
        unsigned prev = atomicAdd(&g_done, 1u);
        if (prev == (unsigned)(gridDim.x - 1)) {
            float total = atomicAdd(&g_loss, 0.0f);  // ordered read
            out[0] = total * (1.0f / (float)NT);
            g_done = 0u;
        }
    }
}

// ---------------------------------------------------------------------------
extern "C" void kernel_launch(void* const* d_in, const int* in_sizes, int n_in,
                              void* d_out, int out_size) {
    const float* logits = (const float*)d_in[0];
    const float* labels = (const float*)d_in[1];
    const int*   mask   = (const int*)d_in[2];
    const void*  ad     = d_in[3];
    (void)in_sizes; (void)n_in; (void)out_size;

    cudaFuncSetAttribute(k_lse_mma, cudaFuncAttributeMaxDynamicSharedMemorySize, SMEM_SZ);

    k_prep<<<257, 256>>>(logits, labels, ad, mask);
    dim3 grid(NT / TM, NSTRIPE);
    k_lse_mma<<<grid, 512, SMEM_SZ>>>();
    k_pairs<<<NT / GROWS, 256>>>(logits, labels, mask, (float*)d_out);
}